// round 15
// baseline (speedup 1.0000x reference)
#include <cuda_runtime.h>
#include <cuda_fp16.h>
#include <stdint.h>
#include <math.h>

typedef unsigned int u32;

#define C_DIM 512
#define N_DIM 4096
#define MAXB  4

// -------- scratch (__device__ globals) --------------------------------------
__device__ __half g_xs[MAXB * C_DIM * N_DIM];   // xn single fp16
__device__ __half g_qs[MAXB * C_DIM * N_DIM];   // q single fp16
__device__ __half g_ks[MAXB * C_DIM * N_DIM];   // k single fp16
__device__ __half g_vs[MAXB * C_DIM * N_DIM];   // v single fp16
__device__ __half g_vps[MAXB * C_DIM * N_DIM];  // V' = Wp.v single fp16
__device__ __half g_ws[4 * C_DIM * C_DIM];      // weights single fp16 (q,k,v,p)
__device__ __half g_attn[MAXB * (size_t)N_DIM * N_DIM];  // S fp16 (134 MB)
__device__ __half g_ps[MAXB * (size_t)N_DIM * N_DIM];    // P fp16 (134 MB)

// ============================================================================
// Helpers
// ============================================================================
__device__ __forceinline__ void single_store2(__half* C, size_t o, float x, float y)
{
    __half2 t(__float2half(x), __float2half(y));
    *(u32*)&C[o] = *(u32*)&t;
}

__device__ __forceinline__ u32 saddr(const void* p)
{
    return (u32)__cvta_generic_to_shared(p);
}

__device__ __forceinline__ void cp16(u32 dst, const void* src)
{
    asm volatile("cp.async.cg.shared.global [%0], [%1], 16;\n" :: "r"(dst), "l"(src));
}
__device__ __forceinline__ void cp_commit()
{
    asm volatile("cp.async.commit_group;\n");
}
template <int NN_>
__device__ __forceinline__ void cp_wait()
{
    asm volatile("cp.async.wait_group %0;\n" :: "n"(NN_));
}

__device__ __forceinline__ void ldsm4(u32* r, u32 a)
{
    asm volatile("ldmatrix.sync.aligned.m8n8.x4.shared.b16 {%0,%1,%2,%3}, [%4];\n"
        : "=r"(r[0]), "=r"(r[1]), "=r"(r[2]), "=r"(r[3]) : "r"(a));
}
__device__ __forceinline__ void ldsm4t(u32* r, u32 a)
{
    asm volatile("ldmatrix.sync.aligned.m8n8.x4.trans.shared.b16 {%0,%1,%2,%3}, [%4];\n"
        : "=r"(r[0]), "=r"(r[1]), "=r"(r[2]), "=r"(r[3]) : "r"(a));
}
__device__ __forceinline__ void mma_f16(float* c, const u32* a, u32 b0, u32 b1)
{
    asm volatile(
        "mma.sync.aligned.m16n8k16.row.col.f32.f16.f16.f32 "
        "{%0,%1,%2,%3}, {%4,%5,%6,%7}, {%8,%9}, {%0,%1,%2,%3};\n"
        : "+f"(c[0]), "+f"(c[1]), "+f"(c[2]), "+f"(c[3])
        : "r"(a[0]), "r"(a[1]), "r"(a[2]), "r"(a[3]), "r"(b0), "r"(b1));
}

// ============================================================================
// fp32 -> single fp16, all 4 weight matrices in one launch (grid.y = matrix)
// ============================================================================
__global__ void convert4_kernel(const float* __restrict__ wq,
                                const float* __restrict__ wk,
                                const float* __restrict__ wv,
                                const float* __restrict__ wp,
                                __half* __restrict__ h, int n4)
{
    int i = blockIdx.x * blockDim.x + threadIdx.x;
    if (i >= n4) return;
    int sel = blockIdx.y;
    const float* in = (sel == 0) ? wq : (sel == 1) ? wk : (sel == 2) ? wv : wp;
    size_t off = (size_t)sel * n4 * 4;
    float4 v = ((const float4*)in)[i];
    single_store2(h + off, (size_t)i * 4,     v.x, v.y);
    single_store2(h + off, (size_t)i * 4 + 2, v.z, v.w);
}

// ============================================================================
// GroupNorm: 32 groups, 16 ch/group, eps=1e-5; writes single fp16
// ============================================================================
__global__ void groupnorm_kernel(const float* __restrict__ x,
                                 const float* __restrict__ w,
                                 const float* __restrict__ b,
                                 __half* __restrict__ os)
{
    const int CPG = 16;
    const int CNT = CPG * N_DIM;
    int bg = blockIdx.x;
    int g  = bg & 31;
    int bb = bg >> 5;
    size_t base = ((size_t)bb * C_DIM + (size_t)g * CPG) * N_DIM;
    const float4* x4 = (const float4*)(x + base);
    int tid = threadIdx.x;

    float s = 0.f, ss = 0.f;
    for (int i = tid; i < CNT / 4; i += blockDim.x) {
        float4 v = x4[i];
        s  += v.x + v.y + v.z + v.w;
        ss += v.x * v.x + v.y * v.y + v.z * v.z + v.w * v.w;
    }
    __shared__ float rs[8], rss[8];
    #pragma unroll
    for (int o = 16; o; o >>= 1) {
        s  += __shfl_xor_sync(0xffffffffu, s,  o);
        ss += __shfl_xor_sync(0xffffffffu, ss, o);
    }
    int wid = tid >> 5;
    int lid = tid & 31;
    if (lid == 0) { rs[wid] = s; rss[wid] = ss; }
    __syncthreads();
    if (tid == 0) {
        float ts = 0.f, tss = 0.f;
        int nw = blockDim.x >> 5;
        for (int i = 0; i < nw; i++) { ts += rs[i]; tss += rss[i]; }
        rs[0] = ts; rss[0] = tss;
    }
    __syncthreads();
    float mu   = rs[0] / (float)CNT;
    float var  = rss[0] / (float)CNT - mu * mu;
    float rsig = rsqrtf(var + 1e-5f);

    for (int i = tid; i < CNT / 4; i += blockDim.x) {
        int c = g * CPG + (i >> 10);
        float sc = w[c] * rsig;
        float sh = b[c] - mu * sc;
        float4 v = x4[i];
        size_t o = base + (size_t)i * 4;
        single_store2(os, o,     v.x * sc + sh, v.y * sc + sh);
        single_store2(os, o + 2, v.z * sc + sh, v.w * sc + sh);
    }
}

// ============================================================================
// Pipelined fp16 tensor-core GEMM (cp.async, NST stages).
//   C[m,n] = alpha * sum_k A(m,k)*B(k,n)   (pure single-fp16, 1 MMA/tile)
//   TA/TB: storage orientation. BK: 32/64. BN: 128 (2 CTA/SM, 64x32 warp tile)
//   or 256 (1 CTA/SM, 64x64 warp tile). NST: pipeline stages.
//   OMODE: 0 = fp32 out (+row bias, +res)
//          1 = single fp16 out (Ch) (+row bias)
//          2 = fused-QKV routing (blockIdx.y: 0-3=q,4-7=k,8-11=v; single out)
// Conflict-free smem strides: narrow rows 56 (BK32) / 72 (BK64); wide rows BN+8.
// ============================================================================
template <bool TA, bool TB, int OMODE, int BK, int BN, int NST>
__global__ __launch_bounds__(256, (BN == 128) ? 2 : 1)
void pgemm_kernel(const __half* __restrict__ Ag,
                  const __half* __restrict__ Bg,
                  float* __restrict__ Cf,
                  __half* __restrict__ Ch,
                  __half* __restrict__ Qs,
                  __half* __restrict__ Ks,
                  __half* __restrict__ Vs,
                  int K, int lda, int ldb, int ldc,
                  long long sA, long long sB, long long sC,
                  const float* __restrict__ bias,
                  const float* __restrict__ bias2,
                  const float* __restrict__ bias3,
                  const float* __restrict__ res, long long sRes,
                  float alpha)
{
    const int PAD = (BK == 32) ? 56 : (BK + 8);
    const int AST = TA ? 136 : PAD;
    const int BST = TB ? PAD : (BN + 8);
    const int ASZ = TA ? (BK * AST) : (128 * AST);
    const int BSZ = TB ? (BN * BST) : (BK * BST);
    const int STAGE = ASZ + BSZ;
    const int KD  = BK / 8;          // 16B chunks per narrow row
    const int NKS = BK / 16;
    const int NT  = BN / 32;         // n-tiles (8-wide pairs) per warp
    const int NP  = BN / 64;         // B ldsm.x4 per k16
    const int RITA = (BK * 128) / 2048;
    const int RITB = (BK * BN)  / 2048;
    const int BD  = BN / 8;          // 16B chunks per wide B row

    extern __shared__ __align__(16) char smraw[];
    __half* sm = (__half*)smraw;

    int z = blockIdx.z;
    Ag += (long long)z * sA;
    Bg += (long long)z * sB;

    int sel = 0;
    int m0;
    if (OMODE == 2) {
        sel = blockIdx.y >> 2;
        m0  = (blockIdx.y & 3) * 128;
        Ag += (long long)sel * C_DIM * C_DIM;
        Qs += (long long)z * sC;
        Ks += (long long)z * sC;
        Vs += (long long)z * sC;
    } else {
        m0 = blockIdx.y * 128;
        if (OMODE == 1) Ch += (long long)z * sC;
        else            Cf += (long long)z * sC;
        if (OMODE == 0 && res) res += (long long)z * sRes;
    }

    int n0 = blockIdx.x * BN;
    int tid  = threadIdx.x;
    int lane = tid & 31;
    int wid  = tid >> 5;
    int m_w = (wid >> 2) * 64;
    int n_w = (wid & 3) * (BN / 4);

    int a_base, b_base;
    if (!TA) {
        a_base = (m_w + (lane & 15)) * AST + ((lane >> 4) * 8);
    } else {
        a_base = (((lane >> 4) & 1) * 8 + (lane & 7)) * AST
               + m_w + ((lane >> 3) & 1) * 8;
    }
    if (!TB) {
        b_base = (((lane >> 3) & 1) * 8 + (lane & 7)) * BST
               + n_w + ((lane >> 4) & 1) * 8;
    } else {
        b_base = (n_w + ((lane >> 4) & 1) * 8 + (lane & 7)) * BST
               + ((lane >> 3) & 1) * 8;
    }

    float c[4][NT][4];
    #pragma unroll
    for (int i = 0; i < 4; i++) {
        #pragma unroll
        for (int j = 0; j < NT; j++) {
            #pragma unroll
            for (int t = 0; t < 4; t++) c[i][j][t] = 0.f;
        }
    }

    int KT = K / BK;

    auto load_stage = [&](int st, int k0) {
        __half* sA = sm + st * STAGE;
        __half* sB = sA + ASZ;
        #pragma unroll
        for (int r = 0; r < RITA; r++) {
            int i = tid + r * 256;
            if (!TA) {
                int m  = i / KD;
                int kq = (i % KD) * 8;
                cp16(saddr(sA + m * AST + kq),
                     Ag + (size_t)(m0 + m) * lda + k0 + kq);
            } else {
                int k  = i >> 4;
                int mq = (i & 15) * 8;
                cp16(saddr(sA + k * AST + mq),
                     Ag + (size_t)(k0 + k) * lda + m0 + mq);
            }
        }
        #pragma unroll
        for (int r = 0; r < RITB; r++) {
            int i = tid + r * 256;
            if (!TB) {
                int k  = i / BD;
                int nq = (i % BD) * 8;
                cp16(saddr(sB + k * BST + nq),
                     Bg + (size_t)(k0 + k) * ldb + n0 + nq);
            } else {
                int n  = i / KD;
                int kq = (i % KD) * 8;
                cp16(saddr(sB + n * BST + kq),
                     Bg + (size_t)(n0 + n) * ldb + k0 + kq);
            }
        }
    };

    #pragma unroll
    for (int s = 0; s < NST - 1; s++) {
        if (s < KT) load_stage(s, s * BK);
        cp_commit();
    }

    for (int kt = 0; kt < KT; kt++) {
        cp_wait<NST - 2>();
        __syncthreads();

        int pf = kt + NST - 1;
        if (pf < KT) load_stage(pf % NST, pf * BK);
        cp_commit();

        int st = kt % NST;
        const __half* pA = sm + st * STAGE;
        const __half* pB = pA + ASZ;

        #pragma unroll
        for (int ks = 0; ks < NKS; ks++) {
            int aoff = a_base + (TA ? ks * 16 * AST : ks * 16);
            int boff = b_base + (TB ? ks * 16 : ks * 16 * BST);

            u32 ah[4][4], bh[NP][4];
            #pragma unroll
            for (int mt = 0; mt < 4; mt++) {
                int o = aoff + (TA ? mt * 16 : mt * 16 * AST);
                if (TA) ldsm4t(ah[mt], saddr(pA + o));
                else    ldsm4 (ah[mt], saddr(pA + o));
            }
            #pragma unroll
            for (int p = 0; p < NP; p++) {
                int o = boff + (TB ? p * 16 * BST : p * 16);
                if (TB) ldsm4 (bh[p], saddr(pB + o));
                else    ldsm4t(bh[p], saddr(pB + o));
            }
            #pragma unroll
            for (int mt = 0; mt < 4; mt++) {
                #pragma unroll
                for (int nt = 0; nt < NT; nt++) {
                    int p = nt >> 1;
                    int q = (nt & 1) * 2;
                    mma_f16(c[mt][nt], ah[mt], bh[p][q], bh[p][q + 1]);
                }
            }
        }
        __syncthreads();
    }

    // ---- epilogue ----
    const float* bp_ = bias;
    __half* So = (OMODE == 1) ? Ch : Qs;
    if (OMODE == 2) {
        if (sel == 1)      { bp_ = bias2; So = Ks; }
        else if (sel == 2) { bp_ = bias3; So = Vs; }
    }

    int g  = lane >> 2;
    int tq = lane & 3;
    #pragma unroll
    for (int mt = 0; mt < 4; mt++) {
        int mr0 = m0 + m_w + mt * 16 + g;
        int mr1 = mr0 + 8;
        float b0v = bp_ ? bp_[mr0] : 0.f;
        float b1v = bp_ ? bp_[mr1] : 0.f;
        #pragma unroll
        for (int nt = 0; nt < NT; nt++) {
            int nc = n0 + n_w + nt * 8 + tq * 2;
            size_t o0 = (size_t)mr0 * ldc + nc;
            size_t o1 = (size_t)mr1 * ldc + nc;
            float v00 = c[mt][nt][0] * alpha + b0v;
            float v01 = c[mt][nt][1] * alpha + b0v;
            float v10 = c[mt][nt][2] * alpha + b1v;
            float v11 = c[mt][nt][3] * alpha + b1v;
            if (OMODE == 0) {
                if (res) {
                    float2 r0 = *(const float2*)&res[o0];
                    float2 r1 = *(const float2*)&res[o1];
                    v00 += r0.x; v01 += r0.y;
                    v10 += r1.x; v11 += r1.y;
                }
                float2 w0; w0.x = v00; w0.y = v01;
                float2 w1; w1.x = v10; w1.y = v11;
                *(float2*)&Cf[o0] = w0;
                *(float2*)&Cf[o1] = w1;
            } else {
                single_store2(So, o0, v00, v01);
                single_store2(So, o1, v10, v11);
            }
        }
    }
}

// ============================================================================
// Row softmax over fp16 attn[b,i,:] (4096), writes fp16 P.
// ============================================================================
__global__ void softmax_kernel(const __half* __restrict__ attn,
                               __half* __restrict__ ps)
{
    size_t row = blockIdx.x;
    const uint4* p = (const uint4*)(attn + row * N_DIM);
    uint4* q = (uint4*)(ps + row * N_DIM);
    int tid = threadIdx.x;
    __shared__ float sh[8];

    float v[2][8];
    float mx = -1e30f;
    #pragma unroll
    for (int i = 0; i < 2; i++) {
        uint4 u = p[tid + i * 256];
        u32 w[4] = {u.x, u.y, u.z, u.w};
        #pragma unroll
        for (int j = 0; j < 4; j++) {
            float2 f = __half22float2(*(__half2*)&w[j]);
            v[i][j * 2]     = f.x;
            v[i][j * 2 + 1] = f.y;
            mx = fmaxf(mx, fmaxf(f.x, f.y));
        }
    }
    #pragma unroll
    for (int o = 16; o; o >>= 1) mx = fmaxf(mx, __shfl_xor_sync(0xffffffffu, mx, o));
    if ((tid & 31) == 0) sh[tid >> 5] = mx;
    __syncthreads();
    if (tid == 0) {
        float t = sh[0];
        for (int i = 1; i < 8; i++) t = fmaxf(t, sh[i]);
        sh[0] = t;
    }
    __syncthreads();
    mx = sh[0];
    __syncthreads();

    float sum = 0.f;
    #pragma unroll
    for (int i = 0; i < 2; i++) {
        #pragma unroll
        for (int j = 0; j < 8; j++) {
            v[i][j] = __expf(v[i][j] - mx);
            sum += v[i][j];
        }
    }
    #pragma unroll
    for (int o = 16; o; o >>= 1) sum += __shfl_xor_sync(0xffffffffu, sum, o);
    if ((tid & 31) == 0) sh[tid >> 5] = sum;
    __syncthreads();
    if (tid == 0) {
        float t = 0.f;
        for (int i = 0; i < 8; i++) t += sh[i];
        sh[0] = t;
    }
    __syncthreads();
    float inv = 1.f / sh[0];

    #pragma unroll
    for (int i = 0; i < 2; i++) {
        uint4 u;
        u32* w = (u32*)&u;
        #pragma unroll
        for (int j = 0; j < 4; j++) {
            __half2 t(__float2half(v[i][j * 2] * inv),
                      __float2half(v[i][j * 2 + 1] * inv));
            w[j] = *(u32*)&t;
        }
        q[tid + i * 256] = u;
    }
}

// ============================================================================
// Host launcher
// ============================================================================
static int stage_elems(bool ta, bool tb, int bk, int bn)
{
    int pad = (bk == 32) ? 56 : (bk + 8);
    int AST = ta ? 136 : pad;
    int BST = tb ? pad : (bn + 8);
    int ASZ = ta ? (bk * AST) : (128 * AST);
    int BSZ = tb ? (bn * BST) : (bk * BST);
    return ASZ + BSZ;
}

extern "C" void kernel_launch(void* const* d_in, const int* in_sizes, int n_in,
                              void* d_out, int out_size)
{
    const float* x   = (const float*)d_in[0];
    const float* gnw = (const float*)d_in[1];
    const float* gnb = (const float*)d_in[2];
    const float* wq  = (const float*)d_in[3];
    const float* bq  = (const float*)d_in[4];
    const float* wk  = (const float*)d_in[5];
    const float* bk  = (const float*)d_in[6];
    const float* wv  = (const float*)d_in[7];
    const float* bv  = (const float*)d_in[8];
    const float* wp  = (const float*)d_in[9];
    const float* bp  = (const float*)d_in[10];
    float* out = (float*)d_out;

    int B = in_sizes[0] / (C_DIM * N_DIM);
    if (B < 1) B = 1;
    if (B > MAXB) B = MAXB;

    __half *xs, *qs, *ks, *vs, *vps, *ws, *attn, *ps;
    cudaGetSymbolAddress((void**)&xs,  g_xs);
    cudaGetSymbolAddress((void**)&qs,  g_qs);
    cudaGetSymbolAddress((void**)&ks,  g_ks);
    cudaGetSymbolAddress((void**)&vs,  g_vs);
    cudaGetSymbolAddress((void**)&vps, g_vps);
    cudaGetSymbolAddress((void**)&ws,  g_ws);
    cudaGetSymbolAddress((void**)&attn, g_attn);
    cudaGetSymbolAddress((void**)&ps,  g_ps);

    const long long CN = (long long)C_DIM * N_DIM;
    const long long NN = (long long)N_DIM * N_DIM;
    const float scale = 1.0f / sqrtf((float)C_DIM);

    int smQKV = 2 * stage_elems(false, false, 32, 128) * 2;
    int smS   = 3 * stage_elems(true,  false, 64, 256) * 2;
    int smPV  = 3 * stage_elems(false, true,  64, 256) * 2;
    cudaFuncSetAttribute(pgemm_kernel<false, false, 2, 32, 128, 2>,
                         cudaFuncAttributeMaxDynamicSharedMemorySize, smQKV);
    cudaFuncSetAttribute(pgemm_kernel<true, false, 1, 64, 256, 3>,
                         cudaFuncAttributeMaxDynamicSharedMemorySize, smS);
    cudaFuncSetAttribute(pgemm_kernel<false, false, 1, 32, 128, 2>,
                         cudaFuncAttributeMaxDynamicSharedMemorySize, smQKV);
    cudaFuncSetAttribute(pgemm_kernel<false, true, 0, 64, 256, 3>,
                         cudaFuncAttributeMaxDynamicSharedMemorySize, smPV);

    // 1) GroupNorm -> single fp16 xn
    groupnorm_kernel<<<B * 32, 256>>>(x, gnw, gnb, xs);

    // 2) Convert all 4 weight matrices to single fp16 in one launch
    {
        int n4 = C_DIM * C_DIM / 4;
        dim3 grid((n4 + 255) / 256, 4);
        convert4_kernel<<<grid, 256>>>(wq, wk, wv, wp, ws, n4);
    }

    // 3) Fused QKV projection (BN=128) -> single fp16 q/k/v
    {
        dim3 grid(N_DIM / 128, 12, B);
        pgemm_kernel<false, false, 2, 32, 128, 2><<<grid, 256, smQKV>>>(
            ws, xs,
            (float*)0, (__half*)0, qs, ks, vs,
            C_DIM, C_DIM, N_DIM, N_DIM, 0, CN, CN,
            bq, bk, bv, (const float*)0, 0, 1.0f);
    }

    // 4) Scores (BN=256, 64x64 warp tile): attn = fp16(scale * q^T k)
    {
        dim3 grid(N_DIM / 256, N_DIM / 128, B);
        pgemm_kernel<true, false, 1, 64, 256, 3><<<grid, 256, smS>>>(
            qs, ks,
            (float*)0, attn, (__half*)0, (__half*)0, (__half*)0,
            C_DIM, N_DIM, N_DIM, N_DIM, CN, CN, NN,
            (const float*)0, (const float*)0, (const float*)0,
            (const float*)0, 0, scale);
    }

    // 5) V' = Wp . v  (BN=128) -> single fp16
    {
        long long CC = (long long)C_DIM * C_DIM;
        dim3 grid(N_DIM / 128, C_DIM / 128, B);
        pgemm_kernel<false, false, 1, 32, 128, 2><<<grid, 256, smQKV>>>(
            ws + 3 * CC, vs,
            (float*)0, vps, (__half*)0, (__half*)0, (__half*)0,
            C_DIM, C_DIM, N_DIM, N_DIM, 0, CN, CN,
            (const float*)0, (const float*)0, (const float*)0,
            (const float*)0, 0, 1.0f);
    }

    // 6) Softmax -> fp16 P
    softmax_kernel<<<B * N_DIM, 256>>>(attn, ps);

    // 7) Final (BN=256, 64x64 warp tile): out = V'.P + bp + x
    {
        dim3 grid(N_DIM / 256, C_DIM / 128, B);
        pgemm_kernel<false, true, 0, 64, 256, 3><<<grid, 256, smPV>>>(
            vps, ps,
            out, (__half*)0, (__half*)0, (__half*)0, (__half*)0,
            N_DIM, N_DIM, N_DIM, N_DIM, CN, NN, CN,
            bp, (const float*)0, (const float*)0, x, CN, 1.0f);
    }
}

// round 16
// speedup vs baseline: 1.0413x; 1.0413x over previous
#include <cuda_runtime.h>
#include <cuda_fp16.h>
#include <stdint.h>
#include <math.h>

typedef unsigned int u32;

#define C_DIM 512
#define N_DIM 4096
#define MAXB  4

// -------- scratch (__device__ globals) --------------------------------------
__device__ __half g_xs[MAXB * C_DIM * N_DIM];   // xn single fp16 [C][N]
__device__ __half g_qs[MAXB * C_DIM * N_DIM];   // q^T [i][c]
__device__ __half g_ks[MAXB * C_DIM * N_DIM];   // k^T [j][c]
__device__ __half g_vs[MAXB * C_DIM * N_DIM];   // v [c][n]
__device__ __half g_vps[MAXB * C_DIM * N_DIM];  // V' = Wp.v [c][n]
__device__ __half g_ws[4 * C_DIM * C_DIM];      // weights fp16 (q,k,v,p)
__device__ __half g_attn[MAXB * (size_t)N_DIM * N_DIM];  // S fp16 [i][j]
__device__ __half g_ps[MAXB * (size_t)N_DIM * N_DIM];    // P fp16 [i][j]

// ============================================================================
// Helpers
// ============================================================================
__device__ __forceinline__ void single_store2(__half* C, size_t o, float x, float y)
{
    __half2 t(__float2half(x), __float2half(y));
    *(u32*)&C[o] = *(u32*)&t;
}

__device__ __forceinline__ u32 saddr(const void* p)
{
    return (u32)__cvta_generic_to_shared(p);
}

__device__ __forceinline__ void cp16(u32 dst, const void* src)
{
    asm volatile("cp.async.cg.shared.global [%0], [%1], 16;\n" :: "r"(dst), "l"(src));
}
__device__ __forceinline__ void cp_commit()
{
    asm volatile("cp.async.commit_group;\n");
}
template <int NN_>
__device__ __forceinline__ void cp_wait()
{
    asm volatile("cp.async.wait_group %0;\n" :: "n"(NN_));
}

__device__ __forceinline__ void ldsm4(u32* r, u32 a)
{
    asm volatile("ldmatrix.sync.aligned.m8n8.x4.shared.b16 {%0,%1,%2,%3}, [%4];\n"
        : "=r"(r[0]), "=r"(r[1]), "=r"(r[2]), "=r"(r[3]) : "r"(a));
}
__device__ __forceinline__ void ldsm4t(u32* r, u32 a)
{
    asm volatile("ldmatrix.sync.aligned.m8n8.x4.trans.shared.b16 {%0,%1,%2,%3}, [%4];\n"
        : "=r"(r[0]), "=r"(r[1]), "=r"(r[2]), "=r"(r[3]) : "r"(a));
}
__device__ __forceinline__ void mma_f16(float* c, const u32* a, u32 b0, u32 b1)
{
    asm volatile(
        "mma.sync.aligned.m16n8k16.row.col.f32.f16.f16.f32 "
        "{%0,%1,%2,%3}, {%4,%5,%6,%7}, {%8,%9}, {%0,%1,%2,%3};\n"
        : "+f"(c[0]), "+f"(c[1]), "+f"(c[2]), "+f"(c[3])
        : "r"(a[0]), "r"(a[1]), "r"(a[2]), "r"(a[3]), "r"(b0), "r"(b1));
}

// ============================================================================
// fp32 -> single fp16, all 4 weight matrices in one launch (grid.y = matrix)
// ============================================================================
__global__ void convert4_kernel(const float* __restrict__ wq,
                                const float* __restrict__ wk,
                                const float* __restrict__ wv,
                                const float* __restrict__ wp,
                                __half* __restrict__ h, int n4)
{
    int i = blockIdx.x * blockDim.x + threadIdx.x;
    if (i >= n4) return;
    int sel = blockIdx.y;
    const float* in = (sel == 0) ? wq : (sel == 1) ? wk : (sel == 2) ? wv : wp;
    size_t off = (size_t)sel * n4 * 4;
    float4 v = ((const float4*)in)[i];
    single_store2(h + off, (size_t)i * 4,     v.x, v.y);
    single_store2(h + off, (size_t)i * 4 + 2, v.z, v.w);
}

// ============================================================================
// GroupNorm: 32 groups, 16 ch/group, eps=1e-5; writes single fp16
// ============================================================================
__global__ void groupnorm_kernel(const float* __restrict__ x,
                                 const float* __restrict__ w,
                                 const float* __restrict__ b,
                                 __half* __restrict__ os)
{
    const int CPG = 16;
    const int CNT = CPG * N_DIM;
    int bg = blockIdx.x;
    int g  = bg & 31;
    int bb = bg >> 5;
    size_t base = ((size_t)bb * C_DIM + (size_t)g * CPG) * N_DIM;
    const float4* x4 = (const float4*)(x + base);
    int tid = threadIdx.x;

    float s = 0.f, ss = 0.f;
    for (int i = tid; i < CNT / 4; i += blockDim.x) {
        float4 v = x4[i];
        s  += v.x + v.y + v.z + v.w;
        ss += v.x * v.x + v.y * v.y + v.z * v.z + v.w * v.w;
    }
    __shared__ float rs[8], rss[8];
    #pragma unroll
    for (int o = 16; o; o >>= 1) {
        s  += __shfl_xor_sync(0xffffffffu, s,  o);
        ss += __shfl_xor_sync(0xffffffffu, ss, o);
    }
    int wid = tid >> 5;
    int lid = tid & 31;
    if (lid == 0) { rs[wid] = s; rss[wid] = ss; }
    __syncthreads();
    if (tid == 0) {
        float ts = 0.f, tss = 0.f;
        int nw = blockDim.x >> 5;
        for (int i = 0; i < nw; i++) { ts += rs[i]; tss += rss[i]; }
        rs[0] = ts; rss[0] = tss;
    }
    __syncthreads();
    float mu   = rs[0] / (float)CNT;
    float var  = rss[0] / (float)CNT - mu * mu;
    float rsig = rsqrtf(var + 1e-5f);

    for (int i = tid; i < CNT / 4; i += blockDim.x) {
        int c = g * CPG + (i >> 10);
        float sc = w[c] * rsig;
        float sh = b[c] - mu * sc;
        float4 v = x4[i];
        size_t o = base + (size_t)i * 4;
        single_store2(os, o,     v.x * sc + sh, v.y * sc + sh);
        single_store2(os, o + 2, v.z * sc + sh, v.w * sc + sh);
    }
}

// ============================================================================
// Pipelined fp16 tensor-core GEMM (cp.async, NST stages, 2 CTAs/SM).
//   C[m,n] = alpha * sum_k A(m,k)*B(k,n)   (pure single-fp16, 1 MMA/tile)
//   TA/TB: storage orientation. BK: 32 or 64. NST: pipeline stages.
//   OMODE: 0 = fp32 out (+row bias, +res)
//          1 = single fp16 out (Ch) (+row bias)
//          2 = fused-QKV routing (blockIdx.y: 0-3=q,4-7=k,8-11=v; single out)
//          3 = fused q^T/k^T routing (blockIdx.y: 0-31=q,32-63=k; COLUMN bias)
// Conflict-free smem strides: narrow rows 56 (BK32) / 72 (BK64); wide rows 136.
// ============================================================================
template <bool TA, bool TB, int OMODE, int BK, int NST>
__global__ __launch_bounds__(256, 2)
void pgemm_kernel(const __half* __restrict__ Ag,
                  const __half* __restrict__ Bg,
                  float* __restrict__ Cf,
                  __half* __restrict__ Ch,
                  __half* __restrict__ Qs,
                  __half* __restrict__ Ks,
                  __half* __restrict__ Vs,
                  int K, int lda, int ldb, int ldc,
                  long long sA, long long sB, long long sC,
                  const float* __restrict__ bias,
                  const float* __restrict__ bias2,
                  const float* __restrict__ bias3,
                  const float* __restrict__ res, long long sRes,
                  float alpha)
{
    const int PAD = (BK == 32) ? 56 : (BK + 8);
    const int AST = TA ? 136 : PAD;
    const int BST = TB ? PAD : 136;
    const int ASZ = TA ? (BK * AST) : (128 * AST);
    const int BSZ = TB ? (128 * BST) : (BK * BST);
    const int STAGE = ASZ + BSZ;
    const int KD  = BK / 8;
    const int RIT = BK / 16;
    const int NKS = BK / 16;

    extern __shared__ __align__(16) char smraw[];
    __half* sm = (__half*)smraw;

    int z = blockIdx.z;
    Ag += (long long)z * sA;
    Bg += (long long)z * sB;

    int sel = 0;
    int m0;
    if (OMODE == 2) {
        sel = blockIdx.y >> 2;
        m0  = (blockIdx.y & 3) * 128;
        Ag += (long long)sel * C_DIM * C_DIM;
        Qs += (long long)z * sC;
        Ks += (long long)z * sC;
        Vs += (long long)z * sC;
    } else if (OMODE == 3) {
        sel = blockIdx.y >> 5;
        m0  = (blockIdx.y & 31) * 128;
        Bg += (long long)sel * C_DIM * C_DIM;
        Qs += (long long)z * sC;
        Ks += (long long)z * sC;
    } else {
        m0 = blockIdx.y * 128;
        if (OMODE == 1) Ch += (long long)z * sC;
        else            Cf += (long long)z * sC;
        if (OMODE == 0 && res) res += (long long)z * sRes;
    }

    int n0 = blockIdx.x * 128;
    int tid  = threadIdx.x;
    int lane = tid & 31;
    int wid  = tid >> 5;
    int m_w = (wid >> 2) * 64;
    int n_w = (wid & 3) * 32;

    int a_base, b_base;
    if (!TA) {
        a_base = (m_w + (lane & 15)) * AST + ((lane >> 4) * 8);
    } else {
        a_base = (((lane >> 4) & 1) * 8 + (lane & 7)) * AST
               + m_w + ((lane >> 3) & 1) * 8;
    }
    if (!TB) {
        b_base = (((lane >> 3) & 1) * 8 + (lane & 7)) * BST
               + n_w + ((lane >> 4) & 1) * 8;
    } else {
        b_base = (n_w + ((lane >> 4) & 1) * 8 + (lane & 7)) * BST
               + ((lane >> 3) & 1) * 8;
    }

    float c[4][4][4];
    #pragma unroll
    for (int i = 0; i < 4; i++) {
        #pragma unroll
        for (int j = 0; j < 4; j++) {
            #pragma unroll
            for (int t = 0; t < 4; t++) c[i][j][t] = 0.f;
        }
    }

    int KT = K / BK;

    auto load_stage = [&](int st, int k0) {
        __half* sA = sm + st * STAGE;
        __half* sB = sA + ASZ;
        #pragma unroll
        for (int r = 0; r < RIT; r++) {
            int i = tid + r * 256;
            if (!TA) {
                int m  = i / KD;
                int kq = (i % KD) * 8;
                cp16(saddr(sA + m * AST + kq),
                     Ag + (size_t)(m0 + m) * lda + k0 + kq);
            } else {
                int k  = i >> 4;
                int mq = (i & 15) * 8;
                cp16(saddr(sA + k * AST + mq),
                     Ag + (size_t)(k0 + k) * lda + m0 + mq);
            }
            if (!TB) {
                int k  = i >> 4;
                int nq = (i & 15) * 8;
                cp16(saddr(sB + k * BST + nq),
                     Bg + (size_t)(k0 + k) * ldb + n0 + nq);
            } else {
                int n  = i / KD;
                int kq = (i % KD) * 8;
                cp16(saddr(sB + n * BST + kq),
                     Bg + (size_t)(n0 + n) * ldb + k0 + kq);
            }
        }
    };

    #pragma unroll
    for (int s = 0; s < NST - 1; s++) {
        if (s < KT) load_stage(s, s * BK);
        cp_commit();
    }

    for (int kt = 0; kt < KT; kt++) {
        cp_wait<NST - 2>();
        __syncthreads();

        int pf = kt + NST - 1;
        if (pf < KT) load_stage(pf % NST, pf * BK);
        cp_commit();

        int st = kt % NST;
        const __half* pA = sm + st * STAGE;
        const __half* pB = pA + ASZ;

        #pragma unroll
        for (int ks = 0; ks < NKS; ks++) {
            int aoff = a_base + (TA ? ks * 16 * AST : ks * 16);
            int boff = b_base + (TB ? ks * 16 : ks * 16 * BST);

            u32 ah[4][4], bh[2][4];
            #pragma unroll
            for (int mt = 0; mt < 4; mt++) {
                int o = aoff + (TA ? mt * 16 : mt * 16 * AST);
                if (TA) ldsm4t(ah[mt], saddr(pA + o));
                else    ldsm4 (ah[mt], saddr(pA + o));
            }
            #pragma unroll
            for (int p = 0; p < 2; p++) {
                int o = boff + (TB ? p * 16 * BST : p * 16);
                if (TB) ldsm4 (bh[p], saddr(pB + o));
                else    ldsm4t(bh[p], saddr(pB + o));
            }
            #pragma unroll
            for (int mt = 0; mt < 4; mt++) {
                #pragma unroll
                for (int nt = 0; nt < 4; nt++) {
                    int p = nt >> 1;
                    int q = (nt & 1) * 2;
                    mma_f16(c[mt][nt], ah[mt], bh[p][q], bh[p][q + 1]);
                }
            }
        }
        __syncthreads();
    }

    // ---- epilogue ----
    const float* bp_ = bias;
    __half* So = (OMODE == 1) ? Ch : Qs;
    if (OMODE == 2) {
        if (sel == 1)      { bp_ = bias2; So = Ks; }
        else if (sel == 2) { bp_ = bias3; So = Vs; }
    } else if (OMODE == 3) {
        if (sel == 1) { bp_ = bias2; So = Ks; }
    }

    int g  = lane >> 2;
    int tq = lane & 3;
    #pragma unroll
    for (int mt = 0; mt < 4; mt++) {
        int mr0 = m0 + m_w + mt * 16 + g;
        int mr1 = mr0 + 8;
        float b0v = 0.f, b1v = 0.f;
        if (OMODE != 3) {
            b0v = bp_ ? bp_[mr0] : 0.f;
            b1v = bp_ ? bp_[mr1] : 0.f;
        }
        #pragma unroll
        for (int nt = 0; nt < 4; nt++) {
            int nc = n0 + n_w + nt * 8 + tq * 2;
            size_t o0 = (size_t)mr0 * ldc + nc;
            size_t o1 = (size_t)mr1 * ldc + nc;
            float v00, v01, v10, v11;
            if (OMODE == 3) {
                float bc0 = bp_[nc];
                float bc1 = bp_[nc + 1];
                v00 = c[mt][nt][0] + bc0;
                v01 = c[mt][nt][1] + bc1;
                v10 = c[mt][nt][2] + bc0;
                v11 = c[mt][nt][3] + bc1;
            } else {
                v00 = c[mt][nt][0] * alpha + b0v;
                v01 = c[mt][nt][1] * alpha + b0v;
                v10 = c[mt][nt][2] * alpha + b1v;
                v11 = c[mt][nt][3] * alpha + b1v;
            }
            if (OMODE == 0) {
                if (res) {
                    float2 r0 = *(const float2*)&res[o0];
                    float2 r1 = *(const float2*)&res[o1];
                    v00 += r0.x; v01 += r0.y;
                    v10 += r1.x; v11 += r1.y;
                }
                float2 w0; w0.x = v00; w0.y = v01;
                float2 w1; w1.x = v10; w1.y = v11;
                *(float2*)&Cf[o0] = w0;
                *(float2*)&Cf[o1] = w1;
            } else {
                single_store2(So, o0, v00, v01);
                single_store2(So, o1, v10, v11);
            }
        }
    }
}

// ============================================================================
// Row softmax over fp16 attn[b,i,:] (4096), writes fp16 P.
// ============================================================================
__global__ void softmax_kernel(const __half* __restrict__ attn,
                               __half* __restrict__ ps)
{
    size_t row = blockIdx.x;
    const uint4* p = (const uint4*)(attn + row * N_DIM);
    uint4* q = (uint4*)(ps + row * N_DIM);
    int tid = threadIdx.x;
    __shared__ float sh[8];

    float v[2][8];
    float mx = -1e30f;
    #pragma unroll
    for (int i = 0; i < 2; i++) {
        uint4 u = p[tid + i * 256];
        u32 w[4] = {u.x, u.y, u.z, u.w};
        #pragma unroll
        for (int j = 0; j < 4; j++) {
            float2 f = __half22float2(*(__half2*)&w[j]);
            v[i][j * 2]     = f.x;
            v[i][j * 2 + 1] = f.y;
            mx = fmaxf(mx, fmaxf(f.x, f.y));
        }
    }
    #pragma unroll
    for (int o = 16; o; o >>= 1) mx = fmaxf(mx, __shfl_xor_sync(0xffffffffu, mx, o));
    if ((tid & 31) == 0) sh[tid >> 5] = mx;
    __syncthreads();
    if (tid == 0) {
        float t = sh[0];
        for (int i = 1; i < 8; i++) t = fmaxf(t, sh[i]);
        sh[0] = t;
    }
    __syncthreads();
    mx = sh[0];
    __syncthreads();

    float sum = 0.f;
    #pragma unroll
    for (int i = 0; i < 2; i++) {
        #pragma unroll
        for (int j = 0; j < 8; j++) {
            v[i][j] = __expf(v[i][j] - mx);
            sum += v[i][j];
        }
    }
    #pragma unroll
    for (int o = 16; o; o >>= 1) sum += __shfl_xor_sync(0xffffffffu, sum, o);
    if ((tid & 31) == 0) sh[tid >> 5] = sum;
    __syncthreads();
    if (tid == 0) {
        float t = 0.f;
        for (int i = 0; i < 8; i++) t += sh[i];
        sh[0] = t;
    }
    __syncthreads();
    float inv = 1.f / sh[0];

    #pragma unroll
    for (int i = 0; i < 2; i++) {
        uint4 u;
        u32* w = (u32*)&u;
        #pragma unroll
        for (int j = 0; j < 4; j++) {
            __half2 t(__float2half(v[i][j * 2] * inv),
                      __float2half(v[i][j * 2 + 1] * inv));
            w[j] = *(u32*)&t;
        }
        q[tid + i * 256] = u;
    }
}

// ============================================================================
// Host launcher
// ============================================================================
static int stage_elems(bool ta, bool tb, int bk)
{
    int pad = (bk == 32) ? 56 : (bk + 8);
    int AST = ta ? 136 : pad;
    int BST = tb ? pad : 136;
    int ASZ = ta ? (bk * AST) : (128 * AST);
    int BSZ = tb ? (128 * BST) : (bk * BST);
    return ASZ + BSZ;
}

extern "C" void kernel_launch(void* const* d_in, const int* in_sizes, int n_in,
                              void* d_out, int out_size)
{
    const float* x   = (const float*)d_in[0];
    const float* gnw = (const float*)d_in[1];
    const float* gnb = (const float*)d_in[2];
    const float* wq  = (const float*)d_in[3];
    const float* bq  = (const float*)d_in[4];
    const float* wk  = (const float*)d_in[5];
    const float* bk  = (const float*)d_in[6];
    const float* wv  = (const float*)d_in[7];
    const float* bv  = (const float*)d_in[8];
    const float* wp  = (const float*)d_in[9];
    const float* bp  = (const float*)d_in[10];
    float* out = (float*)d_out;

    int B = in_sizes[0] / (C_DIM * N_DIM);
    if (B < 1) B = 1;
    if (B > MAXB) B = MAXB;

    __half *xs, *qs, *ks, *vs, *vps, *ws, *attn, *ps;
    cudaGetSymbolAddress((void**)&xs,  g_xs);
    cudaGetSymbolAddress((void**)&qs,  g_qs);
    cudaGetSymbolAddress((void**)&ks,  g_ks);
    cudaGetSymbolAddress((void**)&vs,  g_vs);
    cudaGetSymbolAddress((void**)&vps, g_vps);
    cudaGetSymbolAddress((void**)&ws,  g_ws);
    cudaGetSymbolAddress((void**)&attn, g_attn);
    cudaGetSymbolAddress((void**)&ps,  g_ps);

    const long long CN = (long long)C_DIM * N_DIM;
    const long long NN = (long long)N_DIM * N_DIM;
    const long long CC = (long long)C_DIM * C_DIM;
    const float scale = 1.0f / sqrtf((float)C_DIM);

    int smQK  = 2 * stage_elems(true,  true,  32) * 2;
    int smV   = 2 * stage_elems(false, false, 32) * 2;
    int smS   = 3 * stage_elems(false, true,  64) * 2;
    int smPV  = 3 * stage_elems(false, true,  64) * 2;
    cudaFuncSetAttribute(pgemm_kernel<true, true, 3, 32, 2>,
                         cudaFuncAttributeMaxDynamicSharedMemorySize, smQK);
    cudaFuncSetAttribute(pgemm_kernel<false, false, 1, 32, 2>,
                         cudaFuncAttributeMaxDynamicSharedMemorySize, smV);
    cudaFuncSetAttribute(pgemm_kernel<false, true, 1, 64, 3>,
                         cudaFuncAttributeMaxDynamicSharedMemorySize, smS);
    cudaFuncSetAttribute(pgemm_kernel<false, true, 0, 64, 3>,
                         cudaFuncAttributeMaxDynamicSharedMemorySize, smPV);

    // 1) GroupNorm -> single fp16 xn [C][N]
    groupnorm_kernel<<<B * 32, 256>>>(x, gnw, gnb, xs);

    // 2) Convert all 4 weight matrices to single fp16 in one launch
    {
        int n4 = C_DIM * C_DIM / 4;
        dim3 grid((n4 + 255) / 256, 4);
        convert4_kernel<<<grid, 256>>>(wq, wk, wv, wp, ws, n4);
    }

    // 3) Fused q^T/k^T projection: q^T[i][m] = sum_c xn[c,i] W[m,c] + b[m]
    //    A = xn (TA, [C][N]), B = W (TB, [Cout][Cin]); grid.y 0-31=q, 32-63=k
    {
        dim3 grid(C_DIM / 128, 64, B);
        pgemm_kernel<true, true, 3, 32, 2><<<grid, 256, smQK>>>(
            xs, ws,
            (float*)0, (__half*)0, qs, ks, (__half*)0,
            C_DIM, N_DIM, C_DIM, C_DIM, CN, 0, CN,
            bq, bk, (const float*)0, (const float*)0, 0, 1.0f);
    }

    // 4) v[c][n] = Wv . xn + bv   (standard orientation)
    {
        dim3 grid(N_DIM / 128, C_DIM / 128, B);
        pgemm_kernel<false, false, 1, 32, 2><<<grid, 256, smV>>>(
            ws + 2 * CC, xs,
            (float*)0, vs, (__half*)0, (__half*)0, (__half*)0,
            C_DIM, C_DIM, N_DIM, N_DIM, 0, CN, CN,
            bv, (const float*)0, (const float*)0, (const float*)0, 0, 1.0f);
    }

    // 5) Scores (both operands NON-trans): attn[i][j] = fp16(scale * q^T[i,:].k^T[j,:])
    {
        dim3 grid(N_DIM / 128, N_DIM / 128, B);
        pgemm_kernel<false, true, 1, 64, 3><<<grid, 256, smS>>>(
            qs, ks,
            (float*)0, attn, (__half*)0, (__half*)0, (__half*)0,
            C_DIM, C_DIM, C_DIM, N_DIM, CN, CN, NN,
            (const float*)0, (const float*)0, (const float*)0,
            (const float*)0, 0, scale);
    }

    // 6) V' = Wp . v -> single fp16
    {
        dim3 grid(N_DIM / 128, C_DIM / 128, B);
        pgemm_kernel<false, false, 1, 32, 2><<<grid, 256, smV>>>(
            ws + 3 * CC, vs,
            (float*)0, vps, (__half*)0, (__half*)0, (__half*)0,
            C_DIM, C_DIM, N_DIM, N_DIM, 0, CN, CN,
            (const float*)0, (const float*)0, (const float*)0,
            (const float*)0, 0, 1.0f);
    }

    // 7) Softmax -> fp16 P
    softmax_kernel<<<B * N_DIM, 256>>>(attn, ps);

    // 8) Final: out = V'.P + bp + x
    {
        dim3 grid(N_DIM / 128, C_DIM / 128, B);
        pgemm_kernel<false, true, 0, 64, 3><<<grid, 256, smPV>>>(
            vps, ps,
            out, (__half*)0, (__half*)0, (__half*)0, (__half*)0,
            N_DIM, N_DIM, N_DIM, N_DIM, CN, NN, CN,
            bp, (const float*)0, (const float*)0, x, CN, 1.0f);
    }
}

// round 17
// speedup vs baseline: 1.0677x; 1.0254x over previous
#include <cuda_runtime.h>
#include <cuda_fp16.h>
#include <stdint.h>
#include <math.h>

typedef unsigned int u32;

#define C_DIM 512
#define N_DIM 4096
#define MAXB  4

// -------- scratch (__device__ globals) --------------------------------------
__device__ __half g_xs[MAXB * C_DIM * N_DIM];   // xn single fp16 [C][N]
__device__ __half g_qs[MAXB * C_DIM * N_DIM];   // q^T [i][c]
__device__ __half g_ks[MAXB * C_DIM * N_DIM];   // k^T [j][c]
__device__ __half g_vps[MAXB * C_DIM * N_DIM];  // V' = (Wp.Wv).xn + Wp.bv  [c][n]
__device__ __half g_ws[4 * C_DIM * C_DIM];      // weights fp16 (q,k,v,p)
__device__ __half g_wpv[C_DIM * C_DIM];         // combined Wp.Wv fp16
__device__ float  g_bpv[C_DIM];                 // combined bias Wp.bv
__device__ __half g_attn[MAXB * (size_t)N_DIM * N_DIM];  // S fp16 [i][j]
__device__ __half g_ps[MAXB * (size_t)N_DIM * N_DIM];    // P fp16 [i][j]

// ============================================================================
// Helpers
// ============================================================================
__device__ __forceinline__ void single_store2(__half* C, size_t o, float x, float y)
{
    __half2 t(__float2half(x), __float2half(y));
    *(u32*)&C[o] = *(u32*)&t;
}

__device__ __forceinline__ u32 saddr(const void* p)
{
    return (u32)__cvta_generic_to_shared(p);
}

__device__ __forceinline__ void cp16(u32 dst, const void* src)
{
    asm volatile("cp.async.cg.shared.global [%0], [%1], 16;\n" :: "r"(dst), "l"(src));
}
__device__ __forceinline__ void cp_commit()
{
    asm volatile("cp.async.commit_group;\n");
}
template <int NN_>
__device__ __forceinline__ void cp_wait()
{
    asm volatile("cp.async.wait_group %0;\n" :: "n"(NN_));
}

__device__ __forceinline__ void ldsm4(u32* r, u32 a)
{
    asm volatile("ldmatrix.sync.aligned.m8n8.x4.shared.b16 {%0,%1,%2,%3}, [%4];\n"
        : "=r"(r[0]), "=r"(r[1]), "=r"(r[2]), "=r"(r[3]) : "r"(a));
}
__device__ __forceinline__ void ldsm4t(u32* r, u32 a)
{
    asm volatile("ldmatrix.sync.aligned.m8n8.x4.trans.shared.b16 {%0,%1,%2,%3}, [%4];\n"
        : "=r"(r[0]), "=r"(r[1]), "=r"(r[2]), "=r"(r[3]) : "r"(a));
}
__device__ __forceinline__ void mma_f16(float* c, const u32* a, u32 b0, u32 b1)
{
    asm volatile(
        "mma.sync.aligned.m16n8k16.row.col.f32.f16.f16.f32 "
        "{%0,%1,%2,%3}, {%4,%5,%6,%7}, {%8,%9}, {%0,%1,%2,%3};\n"
        : "+f"(c[0]), "+f"(c[1]), "+f"(c[2]), "+f"(c[3])
        : "r"(a[0]), "r"(a[1]), "r"(a[2]), "r"(a[3]), "r"(b0), "r"(b1));
}

// ============================================================================
// fp32 -> single fp16, all 4 weight matrices in one launch (grid.y = matrix)
// ============================================================================
__global__ void convert4_kernel(const float* __restrict__ wq,
                                const float* __restrict__ wk,
                                const float* __restrict__ wv,
                                const float* __restrict__ wp,
                                __half* __restrict__ h, int n4)
{
    int i = blockIdx.x * blockDim.x + threadIdx.x;
    if (i >= n4) return;
    int sel = blockIdx.y;
    const float* in = (sel == 0) ? wq : (sel == 1) ? wk : (sel == 2) ? wv : wp;
    size_t off = (size_t)sel * n4 * 4;
    float4 v = ((const float4*)in)[i];
    single_store2(h + off, (size_t)i * 4,     v.x, v.y);
    single_store2(h + off, (size_t)i * 4 + 2, v.z, v.w);
}

// ============================================================================
// bpv[c] = sum_j Wp[c][j] * bv[j]   (fp32, one warp per output row)
// ============================================================================
__global__ void bias_gemv_kernel(const float* __restrict__ wp,
                                 const float* __restrict__ bv,
                                 float* __restrict__ bpv)
{
    int c = blockIdx.x * (blockDim.x >> 5) + (threadIdx.x >> 5);
    int lid = threadIdx.x & 31;
    if (c >= C_DIM) return;
    float s = 0.f;
    for (int j = lid; j < C_DIM; j += 32)
        s += wp[(size_t)c * C_DIM + j] * bv[j];
    #pragma unroll
    for (int o = 16; o; o >>= 1) s += __shfl_xor_sync(0xffffffffu, s, o);
    if (lid == 0) bpv[c] = s;
}

// ============================================================================
// GroupNorm: 32 groups, 16 ch/group, eps=1e-5; writes single fp16
// ============================================================================
__global__ void groupnorm_kernel(const float* __restrict__ x,
                                 const float* __restrict__ w,
                                 const float* __restrict__ b,
                                 __half* __restrict__ os)
{
    const int CPG = 16;
    const int CNT = CPG * N_DIM;
    int bg = blockIdx.x;
    int g  = bg & 31;
    int bb = bg >> 5;
    size_t base = ((size_t)bb * C_DIM + (size_t)g * CPG) * N_DIM;
    const float4* x4 = (const float4*)(x + base);
    int tid = threadIdx.x;

    float s = 0.f, ss = 0.f;
    for (int i = tid; i < CNT / 4; i += blockDim.x) {
        float4 v = x4[i];
        s  += v.x + v.y + v.z + v.w;
        ss += v.x * v.x + v.y * v.y + v.z * v.z + v.w * v.w;
    }
    __shared__ float rs[8], rss[8];
    #pragma unroll
    for (int o = 16; o; o >>= 1) {
        s  += __shfl_xor_sync(0xffffffffu, s,  o);
        ss += __shfl_xor_sync(0xffffffffu, ss, o);
    }
    int wid = tid >> 5;
    int lid = tid & 31;
    if (lid == 0) { rs[wid] = s; rss[wid] = ss; }
    __syncthreads();
    if (tid == 0) {
        float ts = 0.f, tss = 0.f;
        int nw = blockDim.x >> 5;
        for (int i = 0; i < nw; i++) { ts += rs[i]; tss += rss[i]; }
        rs[0] = ts; rss[0] = tss;
    }
    __syncthreads();
    float mu   = rs[0] / (float)CNT;
    float var  = rss[0] / (float)CNT - mu * mu;
    float rsig = rsqrtf(var + 1e-5f);

    for (int i = tid; i < CNT / 4; i += blockDim.x) {
        int c = g * CPG + (i >> 10);
        float sc = w[c] * rsig;
        float sh = b[c] - mu * sc;
        float4 v = x4[i];
        size_t o = base + (size_t)i * 4;
        single_store2(os, o,     v.x * sc + sh, v.y * sc + sh);
        single_store2(os, o + 2, v.z * sc + sh, v.w * sc + sh);
    }
}

// ============================================================================
// Pipelined fp16 tensor-core GEMM (cp.async, NST stages, 2 CTAs/SM).
//   C[m,n] = alpha * sum_k A(m,k)*B(k,n)   (pure single-fp16, 1 MMA/tile)
//   TA/TB: storage orientation. BK: 32 or 64. NST: pipeline stages.
//   OMODE: 0 = fp32 out (+row bias, +res)
//          1 = single fp16 out (Ch) (+row bias fp32 ptr)
//          3 = fused q^T/k^T routing (blockIdx.y: 0-31=q,32-63=k; COLUMN bias)
// Conflict-free smem strides: narrow rows 56 (BK32) / 72 (BK64); wide rows 136.
// ============================================================================
template <bool TA, bool TB, int OMODE, int BK, int NST>
__global__ __launch_bounds__(256, 2)
void pgemm_kernel(const __half* __restrict__ Ag,
                  const __half* __restrict__ Bg,
                  float* __restrict__ Cf,
                  __half* __restrict__ Ch,
                  __half* __restrict__ Qs,
                  __half* __restrict__ Ks,
                  int K, int lda, int ldb, int ldc,
                  long long sA, long long sB, long long sC,
                  const float* __restrict__ bias,
                  const float* __restrict__ bias2,
                  const float* __restrict__ res, long long sRes,
                  float alpha)
{
    const int PAD = (BK == 32) ? 56 : (BK + 8);
    const int AST = TA ? 136 : PAD;
    const int BST = TB ? PAD : 136;
    const int ASZ = TA ? (BK * AST) : (128 * AST);
    const int BSZ = TB ? (128 * BST) : (BK * BST);
    const int STAGE = ASZ + BSZ;
    const int KD  = BK / 8;
    const int RIT = BK / 16;
    const int NKS = BK / 16;

    extern __shared__ __align__(16) char smraw[];
    __half* sm = (__half*)smraw;

    int z = blockIdx.z;
    Ag += (long long)z * sA;
    Bg += (long long)z * sB;

    int sel = 0;
    int m0;
    if (OMODE == 3) {
        sel = blockIdx.y >> 5;
        m0  = (blockIdx.y & 31) * 128;
        Bg += (long long)sel * C_DIM * C_DIM;
        Qs += (long long)z * sC;
        Ks += (long long)z * sC;
    } else {
        m0 = blockIdx.y * 128;
        if (OMODE == 1) Ch += (long long)z * sC;
        else            Cf += (long long)z * sC;
        if (OMODE == 0 && res) res += (long long)z * sRes;
    }

    int n0 = blockIdx.x * 128;
    int tid  = threadIdx.x;
    int lane = tid & 31;
    int wid  = tid >> 5;
    int m_w = (wid >> 2) * 64;
    int n_w = (wid & 3) * 32;

    int a_base, b_base;
    if (!TA) {
        a_base = (m_w + (lane & 15)) * AST + ((lane >> 4) * 8);
    } else {
        a_base = (((lane >> 4) & 1) * 8 + (lane & 7)) * AST
               + m_w + ((lane >> 3) & 1) * 8;
    }
    if (!TB) {
        b_base = (((lane >> 3) & 1) * 8 + (lane & 7)) * BST
               + n_w + ((lane >> 4) & 1) * 8;
    } else {
        b_base = (n_w + ((lane >> 4) & 1) * 8 + (lane & 7)) * BST
               + ((lane >> 3) & 1) * 8;
    }

    float c[4][4][4];
    #pragma unroll
    for (int i = 0; i < 4; i++) {
        #pragma unroll
        for (int j = 0; j < 4; j++) {
            #pragma unroll
            for (int t = 0; t < 4; t++) c[i][j][t] = 0.f;
        }
    }

    int KT = K / BK;

    auto load_stage = [&](int st, int k0) {
        __half* sA = sm + st * STAGE;
        __half* sB = sA + ASZ;
        #pragma unroll
        for (int r = 0; r < RIT; r++) {
            int i = tid + r * 256;
            if (!TA) {
                int m  = i / KD;
                int kq = (i % KD) * 8;
                cp16(saddr(sA + m * AST + kq),
                     Ag + (size_t)(m0 + m) * lda + k0 + kq);
            } else {
                int k  = i >> 4;
                int mq = (i & 15) * 8;
                cp16(saddr(sA + k * AST + mq),
                     Ag + (size_t)(k0 + k) * lda + m0 + mq);
            }
            if (!TB) {
                int k  = i >> 4;
                int nq = (i & 15) * 8;
                cp16(saddr(sB + k * BST + nq),
                     Bg + (size_t)(k0 + k) * ldb + n0 + nq);
            } else {
                int n  = i / KD;
                int kq = (i % KD) * 8;
                cp16(saddr(sB + n * BST + kq),
                     Bg + (size_t)(n0 + n) * ldb + k0 + kq);
            }
        }
    };

    #pragma unroll
    for (int s = 0; s < NST - 1; s++) {
        if (s < KT) load_stage(s, s * BK);
        cp_commit();
    }

    for (int kt = 0; kt < KT; kt++) {
        cp_wait<NST - 2>();
        __syncthreads();

        int pf = kt + NST - 1;
        if (pf < KT) load_stage(pf % NST, pf * BK);
        cp_commit();

        int st = kt % NST;
        const __half* pA = sm + st * STAGE;
        const __half* pB = pA + ASZ;

        #pragma unroll
        for (int ks = 0; ks < NKS; ks++) {
            int aoff = a_base + (TA ? ks * 16 * AST : ks * 16);
            int boff = b_base + (TB ? ks * 16 : ks * 16 * BST);

            u32 ah[4][4], bh[2][4];
            #pragma unroll
            for (int mt = 0; mt < 4; mt++) {
                int o = aoff + (TA ? mt * 16 : mt * 16 * AST);
                if (TA) ldsm4t(ah[mt], saddr(pA + o));
                else    ldsm4 (ah[mt], saddr(pA + o));
            }
            #pragma unroll
            for (int p = 0; p < 2; p++) {
                int o = boff + (TB ? p * 16 * BST : p * 16);
                if (TB) ldsm4 (bh[p], saddr(pB + o));
                else    ldsm4t(bh[p], saddr(pB + o));
            }
            #pragma unroll
            for (int mt = 0; mt < 4; mt++) {
                #pragma unroll
                for (int nt = 0; nt < 4; nt++) {
                    int p = nt >> 1;
                    int q = (nt & 1) * 2;
                    mma_f16(c[mt][nt], ah[mt], bh[p][q], bh[p][q + 1]);
                }
            }
        }
        __syncthreads();
    }

    // ---- epilogue ----
    const float* bp_ = bias;
    __half* So = (OMODE == 1) ? Ch : Qs;
    if (OMODE == 3) {
        if (sel == 1) { bp_ = bias2; So = Ks; }
    }

    int g  = lane >> 2;
    int tq = lane & 3;
    #pragma unroll
    for (int mt = 0; mt < 4; mt++) {
        int mr0 = m0 + m_w + mt * 16 + g;
        int mr1 = mr0 + 8;
        float b0v = 0.f, b1v = 0.f;
        if (OMODE != 3) {
            b0v = bp_ ? bp_[mr0] : 0.f;
            b1v = bp_ ? bp_[mr1] : 0.f;
        }
        #pragma unroll
        for (int nt = 0; nt < 4; nt++) {
            int nc = n0 + n_w + nt * 8 + tq * 2;
            size_t o0 = (size_t)mr0 * ldc + nc;
            size_t o1 = (size_t)mr1 * ldc + nc;
            float v00, v01, v10, v11;
            if (OMODE == 3) {
                float bc0 = bp_[nc];
                float bc1 = bp_[nc + 1];
                v00 = c[mt][nt][0] + bc0;
                v01 = c[mt][nt][1] + bc1;
                v10 = c[mt][nt][2] + bc0;
                v11 = c[mt][nt][3] + bc1;
            } else {
                v00 = c[mt][nt][0] * alpha + b0v;
                v01 = c[mt][nt][1] * alpha + b0v;
                v10 = c[mt][nt][2] * alpha + b1v;
                v11 = c[mt][nt][3] * alpha + b1v;
            }
            if (OMODE == 0) {
                if (res) {
                    float2 r0 = *(const float2*)&res[o0];
                    float2 r1 = *(const float2*)&res[o1];
                    v00 += r0.x; v01 += r0.y;
                    v10 += r1.x; v11 += r1.y;
                }
                float2 w0; w0.x = v00; w0.y = v01;
                float2 w1; w1.x = v10; w1.y = v11;
                *(float2*)&Cf[o0] = w0;
                *(float2*)&Cf[o1] = w1;
            } else {
                single_store2(So, o0, v00, v01);
                single_store2(So, o1, v10, v11);
            }
        }
    }
}

// ============================================================================
// Row softmax over fp16 attn[b,i,:] (4096), writes fp16 P.
// ============================================================================
__global__ void softmax_kernel(const __half* __restrict__ attn,
                               __half* __restrict__ ps)
{
    size_t row = blockIdx.x;
    const uint4* p = (const uint4*)(attn + row * N_DIM);
    uint4* q = (uint4*)(ps + row * N_DIM);
    int tid = threadIdx.x;
    __shared__ float sh[8];

    float v[2][8];
    float mx = -1e30f;
    #pragma unroll
    for (int i = 0; i < 2; i++) {
        uint4 u = p[tid + i * 256];
        u32 w[4] = {u.x, u.y, u.z, u.w};
        #pragma unroll
        for (int j = 0; j < 4; j++) {
            float2 f = __half22float2(*(__half2*)&w[j]);
            v[i][j * 2]     = f.x;
            v[i][j * 2 + 1] = f.y;
            mx = fmaxf(mx, fmaxf(f.x, f.y));
        }
    }
    #pragma unroll
    for (int o = 16; o; o >>= 1) mx = fmaxf(mx, __shfl_xor_sync(0xffffffffu, mx, o));
    if ((tid & 31) == 0) sh[tid >> 5] = mx;
    __syncthreads();
    if (tid == 0) {
        float t = sh[0];
        for (int i = 1; i < 8; i++) t = fmaxf(t, sh[i]);
        sh[0] = t;
    }
    __syncthreads();
    mx = sh[0];
    __syncthreads();

    float sum = 0.f;
    #pragma unroll
    for (int i = 0; i < 2; i++) {
        #pragma unroll
        for (int j = 0; j < 8; j++) {
            v[i][j] = __expf(v[i][j] - mx);
            sum += v[i][j];
        }
    }
    #pragma unroll
    for (int o = 16; o; o >>= 1) sum += __shfl_xor_sync(0xffffffffu, sum, o);
    if ((tid & 31) == 0) sh[tid >> 5] = sum;
    __syncthreads();
    if (tid == 0) {
        float t = 0.f;
        for (int i = 0; i < 8; i++) t += sh[i];
        sh[0] = t;
    }
    __syncthreads();
    float inv = 1.f / sh[0];

    #pragma unroll
    for (int i = 0; i < 2; i++) {
        uint4 u;
        u32* w = (u32*)&u;
        #pragma unroll
        for (int j = 0; j < 4; j++) {
            __half2 t(__float2half(v[i][j * 2] * inv),
                      __float2half(v[i][j * 2 + 1] * inv));
            w[j] = *(u32*)&t;
        }
        q[tid + i * 256] = u;
    }
}

// ============================================================================
// Host launcher
// ============================================================================
static int stage_elems(bool ta, bool tb, int bk)
{
    int pad = (bk == 32) ? 56 : (bk + 8);
    int AST = ta ? 136 : pad;
    int BST = tb ? pad : 136;
    int ASZ = ta ? (bk * AST) : (128 * AST);
    int BSZ = tb ? (128 * BST) : (bk * BST);
    return ASZ + BSZ;
}

extern "C" void kernel_launch(void* const* d_in, const int* in_sizes, int n_in,
                              void* d_out, int out_size)
{
    const float* x   = (const float*)d_in[0];
    const float* gnw = (const float*)d_in[1];
    const float* gnb = (const float*)d_in[2];
    const float* wq  = (const float*)d_in[3];
    const float* bq  = (const float*)d_in[4];
    const float* wk  = (const float*)d_in[5];
    const float* bk  = (const float*)d_in[6];
    const float* wv  = (const float*)d_in[7];
    const float* bv  = (const float*)d_in[8];
    const float* wp  = (const float*)d_in[9];
    const float* bp  = (const float*)d_in[10];
    float* out = (float*)d_out;

    int B = in_sizes[0] / (C_DIM * N_DIM);
    if (B < 1) B = 1;
    if (B > MAXB) B = MAXB;

    __half *xs, *qs, *ks, *vps, *ws, *wpv, *attn, *ps;
    float* bpv;
    cudaGetSymbolAddress((void**)&xs,  g_xs);
    cudaGetSymbolAddress((void**)&qs,  g_qs);
    cudaGetSymbolAddress((void**)&ks,  g_ks);
    cudaGetSymbolAddress((void**)&vps, g_vps);
    cudaGetSymbolAddress((void**)&ws,  g_ws);
    cudaGetSymbolAddress((void**)&wpv, g_wpv);
    cudaGetSymbolAddress((void**)&bpv, g_bpv);
    cudaGetSymbolAddress((void**)&attn, g_attn);
    cudaGetSymbolAddress((void**)&ps,  g_ps);

    const long long CN = (long long)C_DIM * N_DIM;
    const long long NN = (long long)N_DIM * N_DIM;
    const long long CC = (long long)C_DIM * C_DIM;
    const float scale = 1.0f / sqrtf((float)C_DIM);

    int smQK  = 2 * stage_elems(true,  true,  32) * 2;
    int smV   = 2 * stage_elems(false, false, 32) * 2;
    int smS   = 3 * stage_elems(false, true,  64) * 2;
    int smPV  = 3 * stage_elems(false, true,  64) * 2;
    cudaFuncSetAttribute(pgemm_kernel<true, true, 3, 32, 2>,
                         cudaFuncAttributeMaxDynamicSharedMemorySize, smQK);
    cudaFuncSetAttribute(pgemm_kernel<false, false, 1, 32, 2>,
                         cudaFuncAttributeMaxDynamicSharedMemorySize, smV);
    cudaFuncSetAttribute(pgemm_kernel<false, true, 1, 64, 3>,
                         cudaFuncAttributeMaxDynamicSharedMemorySize, smS);
    cudaFuncSetAttribute(pgemm_kernel<false, true, 0, 64, 3>,
                         cudaFuncAttributeMaxDynamicSharedMemorySize, smPV);

    // 1) GroupNorm -> single fp16 xn [C][N]
    groupnorm_kernel<<<B * 32, 256>>>(x, gnw, gnb, xs);

    // 2) Convert weights to fp16; bpv = Wp.bv (fp32)
    {
        int n4 = C_DIM * C_DIM / 4;
        dim3 grid((n4 + 255) / 256, 4);
        convert4_kernel<<<grid, 256>>>(wq, wk, wv, wp, ws, n4);
        bias_gemv_kernel<<<C_DIM / 8, 256>>>(wp, bv, bpv);
    }

    // 3) Combined weight: Wpv[c][e] = sum_j Wp[c][j] Wv[j][e]  (tiny GEMM)
    //    A = Wp (non-trans, [M][K]), B = Wv ([K][N] n-contig? Wv is [j][e] row-major
    //    = K-major rows of length 512 -> TB=false), fp16 out, no bias.
    {
        dim3 grid(C_DIM / 128, C_DIM / 128, 1);
        pgemm_kernel<false, false, 1, 32, 2><<<grid, 256, smV>>>(
            ws + 3 * CC, ws + 2 * CC,
            (float*)0, wpv, (__half*)0, (__half*)0,
            C_DIM, C_DIM, C_DIM, C_DIM, 0, 0, 0,
            (const float*)0, (const float*)0, (const float*)0, 0, 1.0f);
    }

    // 4) Fused q^T/k^T projection: q^T[i][m] = sum_c xn[c,i] W[m,c] + b[m]
    {
        dim3 grid(C_DIM / 128, 64, B);
        pgemm_kernel<true, true, 3, 32, 2><<<grid, 256, smQK>>>(
            xs, ws,
            (float*)0, (__half*)0, qs, ks,
            C_DIM, N_DIM, C_DIM, C_DIM, CN, 0, CN,
            bq, bk, (const float*)0, 0, 1.0f);
    }

    // 5) V'[c][n] = Wpv . xn + bpv   (replaces v-proj AND V'-proj)
    {
        dim3 grid(N_DIM / 128, C_DIM / 128, B);
        pgemm_kernel<false, false, 1, 32, 2><<<grid, 256, smV>>>(
            wpv, xs,
            (float*)0, vps, (__half*)0, (__half*)0,
            C_DIM, C_DIM, N_DIM, N_DIM, 0, CN, CN,
            bpv, (const float*)0, (const float*)0, 0, 1.0f);
    }

    // 6) Scores (both operands NON-trans): attn[i][j] = fp16(scale * q^T[i,:].k^T[j,:])
    {
        dim3 grid(N_DIM / 128, N_DIM / 128, B);
        pgemm_kernel<false, true, 1, 64, 3><<<grid, 256, smS>>>(
            qs, ks,
            (float*)0, attn, (__half*)0, (__half*)0,
            C_DIM, C_DIM, C_DIM, N_DIM, CN, CN, NN,
            (const float*)0, (const float*)0, (const float*)0, 0, scale);
    }

    // 7) Softmax -> fp16 P
    softmax_kernel<<<B * N_DIM, 256>>>(attn, ps);

    // 8) Final: out = V'.P + bp + x
    {
        dim3 grid(N_DIM / 128, C_DIM / 128, B);
        pgemm_kernel<false, true, 0, 64, 3><<<grid, 256, smPV>>>(
            vps, ps,
            out, (__half*)0, (__half*)0, (__half*)0,
            N_DIM, N_DIM, N_DIM, N_DIM, CN, NN, CN,
            bp, (const float*)0, x, CN, 1.0f);
    }
}